// round 11
// baseline (speedup 1.0000x reference)
#include <cuda_runtime.h>
#include <cuda_fp16.h>

#define N_NODES 50000
#define N_EDGES 800000
#define E_TOT   (N_EDGES + N_NODES)   // 850000 (self-loops appended)
#define F_IN    128
#define HEADS   4
#define C1      32
#define C2      128
#define D1      (HEADS * C1)          // 128
#define D2      (HEADS * C2)          // 512
#define OUT_DIM 2
#define NEG_SLOPE 0.2f

#define SCAN_B  1024
#define SCAN_NB ((N_NODES + SCAN_B - 1) / SCAN_B)   // 49

// ---------------- device scratch (static; no cudaMalloc allowed) ---------------
__device__ float g_xlr1[N_NODES * 2 * D1];   // [xl1|xr1] interleaved rows (stride 256)
__device__ float g_h1[N_NODES * D1];
__device__ float g_xl2[N_NODES * D2];
__device__ float g_xr2[N_NODES * D2];
__device__ int   g_src[E_TOT];
__device__ int   g_dst[E_TOT];
__device__ int   g_deg[N_NODES];
__device__ int   g_rowptr[N_NODES + 1];
__device__ int   g_cursor[N_NODES];
__device__ int   g_csr_src[E_TOT];
__device__ int   g_blocksum[SCAN_NB];

// ---------------- host-side stream/event objects (created pre-main) -------------
static cudaStream_t g_s1, g_s2;
static cudaEvent_t  g_e0, g_e0b, g_e1, g_e2, g_e3;
static const bool g_init = [] {
    cudaStreamCreateWithFlags(&g_s1, cudaStreamNonBlocking);
    cudaStreamCreateWithFlags(&g_s2, cudaStreamNonBlocking);
    cudaEventCreateWithFlags(&g_e0,  cudaEventDisableTiming);
    cudaEventCreateWithFlags(&g_e0b, cudaEventDisableTiming);
    cudaEventCreateWithFlags(&g_e1,  cudaEventDisableTiming);
    cudaEventCreateWithFlags(&g_e2,  cudaEventDisableTiming);
    cudaEventCreateWithFlags(&g_e3,  cudaEventDisableTiming);
    return true;
}();

// ---------------- edge build (dtype detected per block) --------------------------
__global__ void build_edges_kernel(const void* __restrict__ ei) {
    int nz = 0;
    for (int i = threadIdx.x; i < 512; i += blockDim.x)
        nz |= ((const int*)ei)[2 * i + 1];
    nz = __syncthreads_or(nz);
    const bool is64 = (nz == 0);

    int i = blockIdx.x * blockDim.x + threadIdx.x;
    if (i >= E_TOT) return;
    int s, d;
    if (i < N_EDGES) {
        if (is64) {
            const long long* p = (const long long*)ei;
            s = (int)p[i];
            d = (int)p[N_EDGES + i];
        } else {
            const int* p = (const int*)ei;
            s = p[i];
            d = p[N_EDGES + i];
        }
    } else {
        s = d = i - N_EDGES;
    }
    g_src[i] = s;
    g_dst[i] = d;
    atomicAdd(&g_deg[d], 1);
}

// ---------------- parallel exclusive scan (2 kernels) ----------------------------
__global__ void scan1_kernel() {
    __shared__ int sh[SCAN_B];
    const int tid = threadIdx.x;
    const int idx = blockIdx.x * SCAN_B + tid;
    int v = (idx < N_NODES) ? g_deg[idx] : 0;
    sh[tid] = v;
    __syncthreads();
    #pragma unroll
    for (int off = 1; off < SCAN_B; off <<= 1) {
        int t = (tid >= off) ? sh[tid - off] : 0;
        __syncthreads();
        sh[tid] += t;
        __syncthreads();
    }
    if (idx < N_NODES) g_rowptr[idx] = sh[tid] - v;
    if (tid == SCAN_B - 1) g_blocksum[blockIdx.x] = sh[tid];
}

__global__ void scan3_kernel() {
    __shared__ int vals[SCAN_NB];
    __shared__ int off;
    const int tid = threadIdx.x;
    if (tid < SCAN_NB) vals[tid] = g_blocksum[tid];
    __syncthreads();
    if (tid == 0) {
        const int b = (blockIdx.x * blockDim.x) / SCAN_B;
        int acc = 0;
        for (int i = 0; i < b; i++) acc += vals[i];
        off = acc;
    }
    __syncthreads();
    const int idx = blockIdx.x * blockDim.x + tid;
    if (idx < N_NODES) {
        int r = g_rowptr[idx] + off;
        g_rowptr[idx] = r;
        g_cursor[idx] = r;
    }
    if (idx == 0) g_rowptr[N_NODES] = E_TOT;
}

__global__ void scatter_kernel() {
    int i = blockIdx.x * blockDim.x + threadIdx.x;
    if (i >= E_TOT) return;
    int d = g_dst[i];
    int pos = atomicAdd(&g_cursor[d], 1);
    g_csr_src[pos] = g_src[i];
}

// ---------------- TF32 tensor-core GEMM -----------------------------------------
#define TFS 136

__device__ __forceinline__ unsigned f2tf32(float f) {
    unsigned r;
    asm("cvt.rna.tf32.f32 %0, %1;" : "=r"(r) : "f"(f));
    return r;
}

__device__ __forceinline__ void mma_tf32(float* d, unsigned a0, unsigned a1,
                                         unsigned a2, unsigned a3,
                                         unsigned b0, unsigned b1) {
    asm volatile(
        "mma.sync.aligned.m16n8k8.row.col.f32.tf32.tf32.f32 "
        "{%0,%1,%2,%3}, {%4,%5,%6,%7}, {%8,%9}, {%0,%1,%2,%3};"
        : "+f"(d[0]), "+f"(d[1]), "+f"(d[2]), "+f"(d[3])
        : "r"(a0), "r"(a1), "r"(a2), "r"(a3), "r"(b0), "r"(b1));
}

__global__ void __launch_bounds__(256)
sgemm_tf32(const float* __restrict__ A, const float* __restrict__ B,
           float* __restrict__ C, int N, int K, int Mb, int Mc, int c0) {
    __shared__ unsigned As[2][128][16];   // [buf][m][perm k]
    __shared__ unsigned Bs[2][16][TFS];   // [buf][k][n]

    const int tid  = threadIdx.x;
    const int wid  = tid >> 5;
    const int lane = tid & 31;
    const int grp  = lane >> 2;
    const int tig  = lane & 3;
    const int wm   = wid >> 2;
    const int wn   = wid & 3;
    const int n0   = blockIdx.y * 128;
    const int m0   = blockIdx.x * 128;

    float acc[4][4][4] = {};

    auto loadTiles = [&](int buf, int k0) {
        #pragma unroll
        for (int p = 0; p < 2; p++) {
            int idx = p * 256 + tid;
            int row = idx >> 2;
            int c4  = (idx & 3) * 4;
            int gr  = n0 + row;
            float4 v = make_float4(0.f, 0.f, 0.f, 0.f);
            if (gr < N) v = *(const float4*)(A + (size_t)gr * K + k0 + c4);
            const int pb = c4 >> 2;
            As[buf][row][0 * 4 + pb] = f2tf32(v.x);
            As[buf][row][1 * 4 + pb] = f2tf32(v.y);
            As[buf][row][2 * 4 + pb] = f2tf32(v.z);
            As[buf][row][3 * 4 + pb] = f2tf32(v.w);
        }
        #pragma unroll
        for (int p = 0; p < 2; p++) {
            int idx = p * 256 + tid;
            int r = idx >> 5;
            int c = (idx & 31) * 4;
            float4 v = *(const float4*)(B + (size_t)(k0 + r) * Mb + m0 + c);
            Bs[buf][r][c + 0] = f2tf32(v.x);
            Bs[buf][r][c + 1] = f2tf32(v.y);
            Bs[buf][r][c + 2] = f2tf32(v.z);
            Bs[buf][r][c + 3] = f2tf32(v.w);
        }
    };

    loadTiles(0, 0);
    __syncthreads();

    const int nk = K / 16;
    for (int kt = 0; kt < nk; kt++) {
        const int buf = kt & 1;
        if (kt + 1 < nk) loadTiles(buf ^ 1, (kt + 1) * 16);

        uint4 alo[4], ahi[4];
        #pragma unroll
        for (int mi = 0; mi < 4; mi++) {
            int rb = wm * 64 + mi * 16 + grp;
            alo[mi] = *(const uint4*)&As[buf][rb][4 * tig];
            ahi[mi] = *(const uint4*)&As[buf][rb + 8][4 * tig];
        }
        unsigned bfr[4][4];
        #pragma unroll
        for (int ni = 0; ni < 4; ni++) {
            int nb = wn * 32 + ni * 8 + grp;
            bfr[ni][0] = Bs[buf][tig     ][nb];
            bfr[ni][1] = Bs[buf][tig +  4][nb];
            bfr[ni][2] = Bs[buf][tig +  8][nb];
            bfr[ni][3] = Bs[buf][tig + 12][nb];
        }

        #pragma unroll
        for (int mi = 0; mi < 4; mi++) {
            #pragma unroll
            for (int ni = 0; ni < 4; ni++) {
                mma_tf32(acc[mi][ni], alo[mi].x, ahi[mi].x, alo[mi].y, ahi[mi].y,
                         bfr[ni][0], bfr[ni][1]);
                mma_tf32(acc[mi][ni], alo[mi].z, ahi[mi].z, alo[mi].w, ahi[mi].w,
                         bfr[ni][2], bfr[ni][3]);
            }
        }
        __syncthreads();
    }

    #pragma unroll
    for (int mi = 0; mi < 4; mi++) {
        int r0 = n0 + wm * 64 + mi * 16 + grp;
        int r1 = r0 + 8;
        #pragma unroll
        for (int ni = 0; ni < 4; ni++) {
            int col = c0 + m0 + wn * 32 + ni * 8 + tig * 2;
            if (r0 < N)
                *(float2*)(C + (size_t)r0 * Mc + col) = make_float2(acc[mi][ni][0], acc[mi][ni][1]);
            if (r1 < N)
                *(float2*)(C + (size_t)r1 * Mc + col) = make_float2(acc[mi][ni][2], acc[mi][ni][3]);
        }
    }
}

// ---------------- fused GATv2 edge kernel ----------------------------------------
// block = dst node, warp = head. No running max (scores |e| << 88 at this scale:
// softmax ratio identical to max-subtracted reference). Edge indices staged in
// shared memory once per block (4x fewer index loads, LDS->LDG chain). Copy-free
// 4-buffer software pipeline, OOB slots via clamped index + exact w=0 predicate.
template <int C, bool CONCAT, int STRIDE>
__global__ void __launch_bounds__(HEADS * 32)
gat_fused_kernel(const float* __restrict__ xl, const float* __restrict__ xr,
                 const float* __restrict__ att, const float* __restrict__ bias,
                 float* __restrict__ out, float* __restrict__ hout,
                 const float* __restrict__ Wo, const float* __restrict__ bo,
                 float* __restrict__ outp) {
    constexpr int VEC = C / 32;
    constexpr int CHUNK = 128;
    const int d    = blockIdx.x;
    const int h    = threadIdx.x >> 5;
    const int lane = threadIdx.x & 31;

    const size_t row_off = (size_t)h * C + lane * VEC;

    __shared__ int s_idx[CHUNK];

    float xrv[VEC], attv[VEC];
    if constexpr (VEC == 4) {
        float4 t = *(const float4*)(xr + (size_t)d * STRIDE + row_off);
        xrv[0] = t.x; xrv[1] = t.y; xrv[2] = t.z; xrv[3] = t.w;
        t = *(const float4*)(att + row_off);
        attv[0] = t.x; attv[1] = t.y; attv[2] = t.z; attv[3] = t.w;
    } else {
        xrv[0]  = xr[(size_t)d * STRIDE + row_off];
        attv[0] = att[row_off];
    }

    const int row = g_rowptr[d];
    const int end = g_rowptr[d + 1];   // end >= row+1 (self-loop)

    float S = 0.f;
    float V[VEC];
    #pragma unroll
    for (int i = 0; i < VEC; i++) V[i] = 0.f;

    for (int c0 = row; c0 < end; c0 += CHUNK) {
        const int cnt = min(CHUNK, end - c0);
        __syncthreads();
        if (threadIdx.x < cnt) s_idx[threadIdx.x] = g_csr_src[c0 + threadIdx.x];
        __syncthreads();

        // clamped load: safe for any j; padded slots get w=0 below (exact)
        auto ld = [&](int j, float* dst) {
            const int jj = min(j, cnt - 1);
            const float* p = xl + (size_t)s_idx[jj] * STRIDE + row_off;
            if constexpr (VEC == 4) {
                float4 t = *(const float4*)p;
                dst[0] = t.x; dst[1] = t.y; dst[2] = t.z; dst[3] = t.w;
            } else {
                dst[0] = p[0];
            }
        };

        // process edge pair (x0 = edge j, x1 = edge j+1); w predicated exact
        auto proc2 = [&](const float* x0, const float* x1, int j) {
            float p0 = 0.f, p1 = 0.f;
            #pragma unroll
            for (int i = 0; i < VEC; i++) {
                float m0 = x0[i] + xrv[i];
                p0 += (m0 > 0.f ? m0 : NEG_SLOPE * m0) * attv[i];
                float m1 = x1[i] + xrv[i];
                p1 += (m1 > 0.f ? m1 : NEG_SLOPE * m1) * attv[i];
            }
            #pragma unroll
            for (int off = 16; off >= 1; off >>= 1) {
                p0 += __shfl_xor_sync(0xffffffffu, p0, off);
                p1 += __shfl_xor_sync(0xffffffffu, p1, off);
            }
            const float w0 = (j     < cnt) ? __expf(p0) : 0.f;
            const float w1 = (j + 1 < cnt) ? __expf(p1) : 0.f;
            S += w0 + w1;
            #pragma unroll
            for (int i = 0; i < VEC; i++) V[i] += w0 * x0[i] + w1 * x1[i];
        };

        float xA0[VEC], xA1[VEC], xB0[VEC], xB1[VEC];
        ld(0, xA0); ld(1, xA1); ld(2, xB0); ld(3, xB1);

        for (int j = 0; j < cnt; j += 4) {
            proc2(xA0, xA1, j);
            ld(j + 4, xA0); ld(j + 5, xA1);
            proc2(xB0, xB1, j + 2);
            ld(j + 6, xB0); ld(j + 7, xB1);
        }
    }

    const float inv = 1.f / S;

    if constexpr (CONCAT) {
        #pragma unroll
        for (int i = 0; i < VEC; i++) {
            float v = V[i] * inv + bias[row_off + i];
            out[(size_t)d * (HEADS * C) + row_off + i] = v > 0.f ? v : 0.f;
        }
    } else {
        __shared__ float sh[HEADS * C];
        #pragma unroll
        for (int i = 0; i < VEC; i++)
            sh[row_off + i] = V[i] * inv;
        __syncthreads();
        const int c = threadIdx.x;   // 128 threads, C==128
        float v = (sh[c] + sh[C + c] + sh[2 * C + c] + sh[3 * C + c]) * 0.25f
                  + bias[c];
        if (hout) hout[(size_t)d * C + c] = v;

        if (outp) {
            __shared__ float red0[128], red1[128];
            red0[c] = v * Wo[2 * c];
            red1[c] = v * Wo[2 * c + 1];
            __syncthreads();
            #pragma unroll
            for (int s = 64; s > 0; s >>= 1) {
                if (c < s) { red0[c] += red0[c + s]; red1[c] += red1[c + s]; }
                __syncthreads();
            }
            if (c == 0) {
                outp[2 * d + 0] = red0[0] + bo[0];
                outp[2 * d + 1] = red1[0] + bo[1];
            }
        }
    }
}

// ---------------- launch ---------------------------------------------------------
static inline int cdiv(int a, int b) { return (a + b - 1) / b; }

extern "C" void kernel_launch(void* const* d_in, const int* in_sizes, int n_in,
                              void* d_out, int out_size) {
    const float* x    = (const float*)d_in[0];
    const void*  ei   = d_in[1];
    const float* Wl1  = (const float*)d_in[2];
    const float* Wr1  = (const float*)d_in[3];
    const float* att1 = (const float*)d_in[4];
    const float* b1   = (const float*)d_in[5];
    const float* Wl2  = (const float*)d_in[6];
    const float* Wr2  = (const float*)d_in[7];
    const float* att2 = (const float*)d_in[8];
    const float* b2   = (const float*)d_in[9];
    const float* Wo   = (const float*)d_in[10];
    const float* bo   = (const float*)d_in[11];

    float* outf = (float*)d_out;
    float* outp = nullptr;
    float* hp   = nullptr;
    if (out_size >= N_NODES * (OUT_DIM + C2)) { outp = outf; hp = outf + (size_t)N_NODES * OUT_DIM; }
    else if (out_size == N_NODES * C2)        { hp = outf; }
    else                                       { outp = outf; }

    float *xlr1, *h1, *xl2, *xr2;
    int* degp;
    cudaGetSymbolAddress((void**)&xlr1, g_xlr1);
    cudaGetSymbolAddress((void**)&h1,   g_h1);
    cudaGetSymbolAddress((void**)&xl2,  g_xl2);
    cudaGetSymbolAddress((void**)&xr2,  g_xr2);
    cudaGetSymbolAddress((void**)&degp, g_deg);

    const int T = 256;
    cudaStream_t main0 = 0;   // harness capture stream

    // ---- fork: CSR chain on g_s1, gemm1a on main, gemm1b on g_s2 ----
    cudaMemsetAsync(degp, 0, N_NODES * sizeof(int), main0);
    cudaEventRecord(g_e0, main0);
    cudaStreamWaitEvent(g_s1, g_e0, 0);
    cudaStreamWaitEvent(g_s2, g_e0, 0);

    build_edges_kernel<<<cdiv(E_TOT, T), T, 0, g_s1>>>(ei);                  // #1
    {
        dim3 g(1, cdiv(N_NODES, 128));
        sgemm_tf32<<<g, 256, 0, main0>>>(x, Wl1, xlr1, N_NODES, F_IN, D1, 2 * D1, 0);   // #2
        sgemm_tf32<<<g, 256, 0, g_s2 >>>(x, Wr1, xlr1, N_NODES, F_IN, D1, 2 * D1, D1);  // #3
    }
    scan1_kernel<<<SCAN_NB, SCAN_B, 0, g_s1>>>();                            // #4 (ncu slot)
    scan3_kernel<<<cdiv(N_NODES, T), T, 0, g_s1>>>();                        // #5
    scatter_kernel<<<cdiv(E_TOT, T), T, 0, g_s1>>>();                        // #6
    cudaEventRecord(g_e1, g_s1);
    cudaEventRecord(g_e0b, g_s2);
    cudaStreamWaitEvent(main0, g_e1, 0);
    cudaStreamWaitEvent(main0, g_e0b, 0);

    // ---- layer-1 edge phase (needs CSR + both gemm1 halves) ----
    gat_fused_kernel<C1, true, 2 * D1><<<N_NODES, HEADS * 32, 0, main0>>>(   // #7
        xlr1, xlr1 + D1, att1, b1, h1, nullptr, nullptr, nullptr, nullptr);

    // ---- fork: the two layer-2 GEMMs run concurrently ----
    cudaEventRecord(g_e2, main0);
    cudaStreamWaitEvent(g_s1, g_e2, 0);
    {
        dim3 g(D2 / 128, cdiv(N_NODES, 128));
        sgemm_tf32<<<g, 256, 0, main0>>>(h1, Wl2, xl2, N_NODES, D1, D2, D2, 0);  // #8
        sgemm_tf32<<<g, 256, 0, g_s1 >>>(h1, Wr2, xr2, N_NODES, D1, D2, D2, 0);  // #9
    }
    cudaEventRecord(g_e3, g_s1);
    cudaStreamWaitEvent(main0, g_e3, 0);

    // ---- layer-2 edge phase (+ fused decoder) ----
    gat_fused_kernel<C2, false, D2><<<N_NODES, HEADS * 32, 0, main0>>>(       // #10
        xl2, xr2, att2, b2, nullptr, hp, Wo, bo, outp);
}

// round 13
// speedup vs baseline: 1.0664x; 1.0664x over previous
#include <cuda_runtime.h>
#include <cuda_fp16.h>

#define N_NODES 50000
#define N_EDGES 800000
#define E_TOT   (N_EDGES + N_NODES)   // 850000 (self-loops appended)
#define F_IN    128
#define HEADS   4
#define C1      32
#define C2      128
#define D1      (HEADS * C1)          // 128
#define D2      (HEADS * C2)          // 512
#define OUT_DIM 2
#define NEG_SLOPE 0.2f

#define SCAN_B  1024
#define SCAN_NB ((N_NODES + SCAN_B - 1) / SCAN_B)   // 49

// ---------------- device scratch (static; no cudaMalloc allowed) ---------------
__device__ float g_xlr1[N_NODES * 2 * D1];   // [xl1|xr1] interleaved rows (stride 256)
__device__ float g_h1[N_NODES * D1];
__device__ float g_xl2[N_NODES * D2];
__device__ float g_xr2[N_NODES * D2];
__device__ int   g_src[E_TOT];
__device__ int   g_dst[E_TOT];
__device__ int   g_deg[N_NODES];
__device__ int   g_rowptr[N_NODES + 1];
__device__ int   g_cursor[N_NODES];
__device__ int   g_csr_src[E_TOT];
__device__ int   g_blocksum[SCAN_NB];

// ---------------- host-side stream/event objects (created pre-main) -------------
static cudaStream_t g_s1;
static cudaEvent_t  g_e0, g_e1;
static const bool g_init = [] {
    cudaStreamCreateWithFlags(&g_s1, cudaStreamNonBlocking);
    cudaEventCreateWithFlags(&g_e0, cudaEventDisableTiming);
    cudaEventCreateWithFlags(&g_e1, cudaEventDisableTiming);
    return true;
}();

// ---------------- edge build (dtype detected per block) --------------------------
__global__ void build_edges_kernel(const void* __restrict__ ei) {
    int nz = 0;
    for (int i = threadIdx.x; i < 512; i += blockDim.x)
        nz |= ((const int*)ei)[2 * i + 1];
    nz = __syncthreads_or(nz);
    const bool is64 = (nz == 0);

    int i = blockIdx.x * blockDim.x + threadIdx.x;
    if (i >= E_TOT) return;
    int s, d;
    if (i < N_EDGES) {
        if (is64) {
            const long long* p = (const long long*)ei;
            s = (int)p[i];
            d = (int)p[N_EDGES + i];
        } else {
            const int* p = (const int*)ei;
            s = p[i];
            d = p[N_EDGES + i];
        }
    } else {
        s = d = i - N_EDGES;
    }
    g_src[i] = s;
    g_dst[i] = d;
    atomicAdd(&g_deg[d], 1);
}

// ---------------- parallel exclusive scan (2 kernels) ----------------------------
__global__ void scan1_kernel() {
    __shared__ int sh[SCAN_B];
    const int tid = threadIdx.x;
    const int idx = blockIdx.x * SCAN_B + tid;
    int v = (idx < N_NODES) ? g_deg[idx] : 0;
    sh[tid] = v;
    __syncthreads();
    #pragma unroll
    for (int off = 1; off < SCAN_B; off <<= 1) {
        int t = (tid >= off) ? sh[tid - off] : 0;
        __syncthreads();
        sh[tid] += t;
        __syncthreads();
    }
    if (idx < N_NODES) g_rowptr[idx] = sh[tid] - v;
    if (tid == SCAN_B - 1) g_blocksum[blockIdx.x] = sh[tid];
}

__global__ void scan3_kernel() {
    __shared__ int vals[SCAN_NB];
    __shared__ int off;
    const int tid = threadIdx.x;
    if (tid < SCAN_NB) vals[tid] = g_blocksum[tid];
    __syncthreads();
    if (tid == 0) {
        const int b = (blockIdx.x * blockDim.x) / SCAN_B;
        int acc = 0;
        for (int i = 0; i < b; i++) acc += vals[i];
        off = acc;
    }
    __syncthreads();
    const int idx = blockIdx.x * blockDim.x + tid;
    if (idx < N_NODES) {
        int r = g_rowptr[idx] + off;
        g_rowptr[idx] = r;
        g_cursor[idx] = r;
    }
    if (idx == 0) g_rowptr[N_NODES] = E_TOT;
}

__global__ void scatter_kernel() {
    int i = blockIdx.x * blockDim.x + threadIdx.x;
    if (i >= E_TOT) return;
    int d = g_dst[i];
    int pos = atomicAdd(&g_cursor[d], 1);
    g_csr_src[pos] = g_src[i];
}

// ---------------- TF32 tensor-core GEMM (dual B/C, one launch) -------------------
// grid.x = 2*halfX. Blocks [0, halfX) compute Ca = A@Ba; blocks [halfX, 2*halfX)
// compute Cb = A@Bb at column offset coff. Mb = B width, Mc = C row stride.
// NOTE: parameter names must avoid the C1/C2 macros.
#define TFS 136

__device__ __forceinline__ unsigned f2tf32(float f) {
    unsigned r;
    asm("cvt.rna.tf32.f32 %0, %1;" : "=r"(r) : "f"(f));
    return r;
}

__device__ __forceinline__ void mma_tf32(float* d, unsigned a0, unsigned a1,
                                         unsigned a2, unsigned a3,
                                         unsigned b0, unsigned b1) {
    asm volatile(
        "mma.sync.aligned.m16n8k8.row.col.f32.tf32.tf32.f32 "
        "{%0,%1,%2,%3}, {%4,%5,%6,%7}, {%8,%9}, {%0,%1,%2,%3};"
        : "+f"(d[0]), "+f"(d[1]), "+f"(d[2]), "+f"(d[3])
        : "r"(a0), "r"(a1), "r"(a2), "r"(a3), "r"(b0), "r"(b1));
}

__global__ void __launch_bounds__(256)
sgemm_tf32(const float* __restrict__ A,
           const float* __restrict__ Ba, const float* __restrict__ Bb,
           float* __restrict__ Ca, float* __restrict__ Cb,
           int N, int K, int Mb, int Mc, int halfX, int coff) {
    __shared__ unsigned As[2][128][16];   // [buf][m][perm k]
    __shared__ unsigned Bs[2][16][TFS];   // [buf][k][n]

    const bool second = (int)blockIdx.x >= halfX;
    const float* B = second ? Bb : Ba;
    float* Cp      = second ? Cb : Ca;
    const int ccol0 = second ? coff : 0;
    const int m0 = ((int)blockIdx.x % halfX) * 128;

    const int tid  = threadIdx.x;
    const int wid  = tid >> 5;
    const int lane = tid & 31;
    const int grp  = lane >> 2;
    const int tig  = lane & 3;
    const int wm   = wid >> 2;
    const int wn   = wid & 3;
    const int n0   = blockIdx.y * 128;

    float acc[4][4][4] = {};

    auto loadTiles = [&](int buf, int k0) {
        #pragma unroll
        for (int p = 0; p < 2; p++) {
            int idx = p * 256 + tid;
            int row = idx >> 2;
            int c4  = (idx & 3) * 4;
            int gr  = n0 + row;
            float4 v = make_float4(0.f, 0.f, 0.f, 0.f);
            if (gr < N) v = *(const float4*)(A + (size_t)gr * K + k0 + c4);
            const int pb = c4 >> 2;
            As[buf][row][0 * 4 + pb] = f2tf32(v.x);
            As[buf][row][1 * 4 + pb] = f2tf32(v.y);
            As[buf][row][2 * 4 + pb] = f2tf32(v.z);
            As[buf][row][3 * 4 + pb] = f2tf32(v.w);
        }
        #pragma unroll
        for (int p = 0; p < 2; p++) {
            int idx = p * 256 + tid;
            int r = idx >> 5;
            int c = (idx & 31) * 4;
            float4 v = *(const float4*)(B + (size_t)(k0 + r) * Mb + m0 + c);
            Bs[buf][r][c + 0] = f2tf32(v.x);
            Bs[buf][r][c + 1] = f2tf32(v.y);
            Bs[buf][r][c + 2] = f2tf32(v.z);
            Bs[buf][r][c + 3] = f2tf32(v.w);
        }
    };

    loadTiles(0, 0);
    __syncthreads();

    const int nk = K / 16;
    for (int kt = 0; kt < nk; kt++) {
        const int buf = kt & 1;
        if (kt + 1 < nk) loadTiles(buf ^ 1, (kt + 1) * 16);

        uint4 alo[4], ahi[4];
        #pragma unroll
        for (int mi = 0; mi < 4; mi++) {
            int rb = wm * 64 + mi * 16 + grp;
            alo[mi] = *(const uint4*)&As[buf][rb][4 * tig];
            ahi[mi] = *(const uint4*)&As[buf][rb + 8][4 * tig];
        }
        unsigned bfr[4][4];
        #pragma unroll
        for (int ni = 0; ni < 4; ni++) {
            int nb = wn * 32 + ni * 8 + grp;
            bfr[ni][0] = Bs[buf][tig     ][nb];
            bfr[ni][1] = Bs[buf][tig +  4][nb];
            bfr[ni][2] = Bs[buf][tig +  8][nb];
            bfr[ni][3] = Bs[buf][tig + 12][nb];
        }

        #pragma unroll
        for (int mi = 0; mi < 4; mi++) {
            #pragma unroll
            for (int ni = 0; ni < 4; ni++) {
                mma_tf32(acc[mi][ni], alo[mi].x, ahi[mi].x, alo[mi].y, ahi[mi].y,
                         bfr[ni][0], bfr[ni][1]);
                mma_tf32(acc[mi][ni], alo[mi].z, ahi[mi].z, alo[mi].w, ahi[mi].w,
                         bfr[ni][2], bfr[ni][3]);
            }
        }
        __syncthreads();
    }

    #pragma unroll
    for (int mi = 0; mi < 4; mi++) {
        int r0 = n0 + wm * 64 + mi * 16 + grp;
        int r1 = r0 + 8;
        #pragma unroll
        for (int ni = 0; ni < 4; ni++) {
            int col = ccol0 + m0 + wn * 32 + ni * 8 + tig * 2;
            if (r0 < N)
                *(float2*)(Cp + (size_t)r0 * Mc + col) = make_float2(acc[mi][ni][0], acc[mi][ni][1]);
            if (r1 < N)
                *(float2*)(Cp + (size_t)r1 * Mc + col) = make_float2(acc[mi][ni][2], acc[mi][ni][3]);
        }
    }
}

// ---------------- fused GATv2 edge kernel (lane-group edge parallelism) ----------
// block = dst node, warp = head. Lanes split into GROUPS groups of GSIZE; group g
// owns edges j+g. One gather LDG covers GROUPS edges; the log2(GSIZE)-shuffle
// reduce and the single exp are shared across groups in the same instructions.
// No running max (|e| << 88 at this scale: ratio identical to reference).
// OOB groups: clamped index + exact w=0. Per-group S/V merged once via smem.
template <int C, bool CONCAT, int STRIDE, int GROUPS>
__global__ void __launch_bounds__(HEADS * 32)
gat_fused_kernel(const float* __restrict__ xl, const float* __restrict__ xr,
                 const float* __restrict__ att, const float* __restrict__ bias,
                 float* __restrict__ out, float* __restrict__ hout,
                 const float* __restrict__ Wo, const float* __restrict__ bo,
                 float* __restrict__ outp) {
    constexpr int GSIZE = 32 / GROUPS;
    constexpr int VEC   = C / GSIZE;
    constexpr int NV4   = VEC / 4;
    const int d    = blockIdx.x;
    const int h    = threadIdx.x >> 5;
    const int lane = threadIdx.x & 31;
    const int g    = lane / GSIZE;
    const int sl   = lane % GSIZE;
    const int row_off = h * C + sl * VEC;

    float xrv[VEC], attv[VEC];
    #pragma unroll
    for (int i = 0; i < NV4; i++) {
        float4 t = *(const float4*)(xr + (size_t)d * STRIDE + row_off + 4 * i);
        xrv[4*i+0] = t.x; xrv[4*i+1] = t.y; xrv[4*i+2] = t.z; xrv[4*i+3] = t.w;
        t = *(const float4*)(att + row_off + 4 * i);
        attv[4*i+0] = t.x; attv[4*i+1] = t.y; attv[4*i+2] = t.z; attv[4*i+3] = t.w;
    }

    const int row = g_rowptr[d];
    const int end = g_rowptr[d + 1];   // end >= row+1 (self-loop)

    float S = 0.f;
    float V[VEC];
    #pragma unroll
    for (int i = 0; i < VEC; i++) V[i] = 0.f;

    auto ld = [&](int j, float* dst) {
        const int jj = min(j + g, end - 1);            // clamp: OOB groups get w=0
        const float* p = xl + (size_t)g_csr_src[jj] * STRIDE + row_off;
        #pragma unroll
        for (int i = 0; i < NV4; i++) {
            float4 t = ((const float4*)p)[i];
            dst[4*i+0] = t.x; dst[4*i+1] = t.y; dst[4*i+2] = t.z; dst[4*i+3] = t.w;
        }
    };

    auto proc = [&](const float* x, int j) {
        float p = 0.f;
        #pragma unroll
        for (int i = 0; i < VEC; i++) {
            float m = x[i] + xrv[i];
            p += (m > 0.f ? m : NEG_SLOPE * m) * attv[i];
        }
        #pragma unroll
        for (int off = GSIZE / 2; off >= 1; off >>= 1)
            p += __shfl_xor_sync(0xffffffffu, p, off);
        const float w = (j + g < end) ? __expf(p) : 0.f;
        S += w;
        #pragma unroll
        for (int i = 0; i < VEC; i++) V[i] += w * x[i];
    };

    float xa[VEC], xb[VEC];
    ld(row, xa);
    if (row + GROUPS < end) ld(row + GROUPS, xb);

    for (int j = row; j < end; j += 2 * GROUPS) {
        float x0[VEC];
        #pragma unroll
        for (int i = 0; i < VEC; i++) x0[i] = xa[i];
        if (j + 2 * GROUPS < end) ld(j + 2 * GROUPS, xa);
        proc(x0, j);
        if (j + GROUPS < end) {
            float x1[VEC];
            #pragma unroll
            for (int i = 0; i < VEC; i++) x1[i] = xb[i];
            if (j + 3 * GROUPS < end) ld(j + 3 * GROUPS, xb);
            proc(x1, j + GROUPS);
        }
    }

    // ---- merge per-group states ----
    __shared__ float sV[GROUPS][HEADS * C];
    __shared__ float sS[GROUPS][HEADS];
    #pragma unroll
    for (int i = 0; i < VEC; i++) sV[g][row_off + i] = V[i];
    if (sl == 0) sS[g][h] = S;
    __syncthreads();

    const int t = threadIdx.x;   // 128 threads
    if constexpr (CONCAT) {
        const int th = t / C;
        float s = 0.f, v = 0.f;
        #pragma unroll
        for (int gg = 0; gg < GROUPS; gg++) { s += sS[gg][th]; v += sV[gg][t]; }
        float o = v / s + bias[t];
        out[(size_t)d * (HEADS * C) + t] = o > 0.f ? o : 0.f;
    } else {
        float acc = 0.f;
        #pragma unroll
        for (int hh = 0; hh < HEADS; hh++) {
            float s = 0.f, v = 0.f;
            #pragma unroll
            for (int gg = 0; gg < GROUPS; gg++) { s += sS[gg][hh]; v += sV[gg][hh * C + t]; }
            acc += v / s;
        }
        float o = acc * 0.25f + bias[t];
        if (hout) hout[(size_t)d * C + t] = o;

        if (outp) {
            __shared__ float red0[128], red1[128];
            red0[t] = o * Wo[2 * t];
            red1[t] = o * Wo[2 * t + 1];
            __syncthreads();
            #pragma unroll
            for (int s2 = 64; s2 > 0; s2 >>= 1) {
                if (t < s2) { red0[t] += red0[t + s2]; red1[t] += red1[t + s2]; }
                __syncthreads();
            }
            if (t == 0) {
                outp[2 * d + 0] = red0[0] + bo[0];
                outp[2 * d + 1] = red1[0] + bo[1];
            }
        }
    }
}

// ---------------- launch ---------------------------------------------------------
static inline int cdiv(int a, int b) { return (a + b - 1) / b; }

extern "C" void kernel_launch(void* const* d_in, const int* in_sizes, int n_in,
                              void* d_out, int out_size) {
    const float* x    = (const float*)d_in[0];
    const void*  ei   = d_in[1];
    const float* Wl1  = (const float*)d_in[2];
    const float* Wr1  = (const float*)d_in[3];
    const float* att1 = (const float*)d_in[4];
    const float* b1   = (const float*)d_in[5];
    const float* Wl2  = (const float*)d_in[6];
    const float* Wr2  = (const float*)d_in[7];
    const float* att2 = (const float*)d_in[8];
    const float* b2   = (const float*)d_in[9];
    const float* Wo   = (const float*)d_in[10];
    const float* bo   = (const float*)d_in[11];

    float* outf = (float*)d_out;
    float* outp = nullptr;
    float* hp   = nullptr;
    if (out_size >= N_NODES * (OUT_DIM + C2)) { outp = outf; hp = outf + (size_t)N_NODES * OUT_DIM; }
    else if (out_size == N_NODES * C2)        { hp = outf; }
    else                                       { outp = outf; }

    float *xlr1, *h1, *xl2, *xr2;
    int* degp;
    cudaGetSymbolAddress((void**)&xlr1, g_xlr1);
    cudaGetSymbolAddress((void**)&h1,   g_h1);
    cudaGetSymbolAddress((void**)&xl2,  g_xl2);
    cudaGetSymbolAddress((void**)&xr2,  g_xr2);
    cudaGetSymbolAddress((void**)&degp, g_deg);

    const int T = 256;
    cudaStream_t main0 = 0;   // harness capture stream

    // ---- fork: CSR chain on g_s1, layer-1 GEMM on main ----
    cudaMemsetAsync(degp, 0, N_NODES * sizeof(int), main0);
    cudaEventRecord(g_e0, main0);
    cudaStreamWaitEvent(g_s1, g_e0, 0);

    build_edges_kernel<<<cdiv(E_TOT, T), T, 0, g_s1>>>(ei);                  // #1
    {
        dim3 g(2, cdiv(N_NODES, 128));   // block 0: Wl1 -> cols [0,128); block 1: Wr1 -> [128,256)
        sgemm_tf32<<<g, 256, 0, main0>>>(x, Wl1, Wr1, xlr1, xlr1,
                                         N_NODES, F_IN, D1, 2 * D1, 1, D1);  // #2
    }
    scan1_kernel<<<SCAN_NB, SCAN_B, 0, g_s1>>>();                            // #3
    scan3_kernel<<<cdiv(N_NODES, T), T, 0, g_s1>>>();                        // #4
    scatter_kernel<<<cdiv(E_TOT, T), T, 0, g_s1>>>();                        // #5
    cudaEventRecord(g_e1, g_s1);
    cudaStreamWaitEvent(main0, g_e1, 0);

    // ---- layer-1 edge phase (4 groups x 8 lanes) ----
    gat_fused_kernel<C1, true, 2 * D1, 4><<<N_NODES, HEADS * 32, 0, main0>>>( // #6
        xlr1, xlr1 + D1, att1, b1, h1, nullptr, nullptr, nullptr, nullptr);

    // ---- layer-2 GEMMs: one launch, both halves ----
    {
        dim3 g(8, cdiv(N_NODES, 128));   // blocks 0-3: Wl2->xl2, 4-7: Wr2->xr2
        sgemm_tf32<<<g, 256, 0, main0>>>(h1, Wl2, Wr2, xl2, xr2,
                                         N_NODES, D1, D2, D2, 4, 0);          // #7
    }

    // ---- layer-2 edge phase (2 groups x 16 lanes, + fused decoder) ----
    gat_fused_kernel<C2, false, D2, 2><<<N_NODES, HEADS * 32, 0, main0>>>(    // #8
        xl2, xr2, att2, b2, nullptr, hp, Wo, bo, outp);
}

// round 15
// speedup vs baseline: 1.1453x; 1.0740x over previous
#include <cuda_runtime.h>
#include <cuda_fp16.h>
#include <cstdint>

#define N_NODES 50000
#define N_EDGES 800000
#define E_TOT   (N_EDGES + N_NODES)   // 850000 (self-loops appended)
#define F_IN    128
#define HEADS   4
#define C1      32
#define C2      128
#define D1      (HEADS * C1)          // 128
#define D2      (HEADS * C2)          // 512
#define OUT_DIM 2
#define NEG_SLOPE 0.2f

#define SCAN_B  1024
#define SCAN_NB ((N_NODES + SCAN_B - 1) / SCAN_B)   // 49

// ---------------- device scratch (static; no cudaMalloc allowed) ---------------
__device__ float g_xlr1[N_NODES * 2 * D1];   // [xl1|xr1] interleaved rows (stride 256)
__device__ float g_h1[N_NODES * D1];
__device__ float g_xl2[N_NODES * D2];
__device__ float g_xr2[N_NODES * D2];
__device__ int   g_src[E_TOT];
__device__ int   g_dst[E_TOT];
__device__ int   g_deg[N_NODES];
__device__ int   g_rowptr[N_NODES + 1];
__device__ int   g_cursor[N_NODES];
__device__ int   g_csr_src[E_TOT];
__device__ int   g_blocksum[SCAN_NB];

// ---------------- host-side stream/event objects (created pre-main) -------------
static cudaStream_t g_s1;
static cudaEvent_t  g_e0, g_e1;
static const bool g_init = [] {
    cudaStreamCreateWithFlags(&g_s1, cudaStreamNonBlocking);
    cudaEventCreateWithFlags(&g_e0, cudaEventDisableTiming);
    cudaEventCreateWithFlags(&g_e1, cudaEventDisableTiming);
    return true;
}();

// ---------------- edge build (dtype detected per block) --------------------------
__global__ void build_edges_kernel(const void* __restrict__ ei) {
    int nz = 0;
    for (int i = threadIdx.x; i < 512; i += blockDim.x)
        nz |= ((const int*)ei)[2 * i + 1];
    nz = __syncthreads_or(nz);
    const bool is64 = (nz == 0);

    int i = blockIdx.x * blockDim.x + threadIdx.x;
    if (i >= E_TOT) return;
    int s, d;
    if (i < N_EDGES) {
        if (is64) {
            const long long* p = (const long long*)ei;
            s = (int)p[i];
            d = (int)p[N_EDGES + i];
        } else {
            const int* p = (const int*)ei;
            s = p[i];
            d = p[N_EDGES + i];
        }
    } else {
        s = d = i - N_EDGES;
    }
    g_src[i] = s;
    g_dst[i] = d;
    atomicAdd(&g_deg[d], 1);
}

// ---------------- parallel exclusive scan (2 kernels) ----------------------------
__global__ void scan1_kernel() {
    __shared__ int sh[SCAN_B];
    const int tid = threadIdx.x;
    const int idx = blockIdx.x * SCAN_B + tid;
    int v = (idx < N_NODES) ? g_deg[idx] : 0;
    sh[tid] = v;
    __syncthreads();
    #pragma unroll
    for (int off = 1; off < SCAN_B; off <<= 1) {
        int t = (tid >= off) ? sh[tid - off] : 0;
        __syncthreads();
        sh[tid] += t;
        __syncthreads();
    }
    if (idx < N_NODES) g_rowptr[idx] = sh[tid] - v;
    if (tid == SCAN_B - 1) g_blocksum[blockIdx.x] = sh[tid];
}

__global__ void scan3_kernel() {
    __shared__ int vals[SCAN_NB];
    __shared__ int off;
    const int tid = threadIdx.x;
    if (tid < SCAN_NB) vals[tid] = g_blocksum[tid];
    __syncthreads();
    if (tid == 0) {
        const int b = (blockIdx.x * blockDim.x) / SCAN_B;
        int acc = 0;
        for (int i = 0; i < b; i++) acc += vals[i];
        off = acc;
    }
    __syncthreads();
    const int idx = blockIdx.x * blockDim.x + tid;
    if (idx < N_NODES) {
        int r = g_rowptr[idx] + off;
        g_rowptr[idx] = r;
        g_cursor[idx] = r;
    }
    if (idx == 0) g_rowptr[N_NODES] = E_TOT;
}

__global__ void scatter_kernel() {
    int i = blockIdx.x * blockDim.x + threadIdx.x;
    if (i >= E_TOT) return;
    int d = g_dst[i];
    int pos = atomicAdd(&g_cursor[d], 1);
    g_csr_src[pos] = g_src[i];
}

// ---------------- FP16 tensor-core GEMM (m16n8k16, fp32 accumulate) --------------
// grid.x = 2*halfX. Blocks [0, halfX) compute Ca = A@Ba; blocks [halfX, 2*halfX)
// compute Cb = A@Bb at column offset coff. Mb = B width, Mc = C row stride.
// A smem: dense half2 k-pairs, permuted so slot 2*tig = kpair tig and slot
// 2*tig+1 = kpair tig+4 -> one 8-byte LDS per A fragment pair; banks
// grp*8 + 2*tig + {0,1} tile 0..31 exactly (conflict-free per 16-lane phase).
// B smem: [kpair][n] half2 (k=2kp, 2kp+1 at col n), stride 136 (banks 8*tig+grp).
__device__ __forceinline__ void mma_f16(float* d, unsigned a0, unsigned a1,
                                        unsigned a2, unsigned a3,
                                        unsigned b0, unsigned b1) {
    asm volatile(
        "mma.sync.aligned.m16n8k16.row.col.f32.f16.f16.f32 "
        "{%0,%1,%2,%3}, {%4,%5,%6,%7}, {%8,%9}, {%0,%1,%2,%3};"
        : "+f"(d[0]), "+f"(d[1]), "+f"(d[2]), "+f"(d[3])
        : "r"(a0), "r"(a1), "r"(a2), "r"(a3), "r"(b0), "r"(b1));
}

__global__ void __launch_bounds__(256)
sgemm_f16(const float* __restrict__ A,
          const float* __restrict__ Ba, const float* __restrict__ Bb,
          float* __restrict__ Ca, float* __restrict__ Cb,
          int N, int K, int Mb, int Mc, int halfX, int coff) {
    __shared__ unsigned As2[2][128][8];    // [buf][m][perm kpair] half2
    __shared__ unsigned Bs2[2][8][136];    // [buf][kpair][n] half2

    const bool second = (int)blockIdx.x >= halfX;
    const float* B = second ? Bb : Ba;
    float* Cp      = second ? Cb : Ca;
    const int ccol0 = second ? coff : 0;
    const int m0 = ((int)blockIdx.x % halfX) * 128;

    const int tid  = threadIdx.x;
    const int wid  = tid >> 5;
    const int lane = tid & 31;
    const int grp  = lane >> 2;
    const int tig  = lane & 3;
    const int wm   = wid >> 2;
    const int wn   = wid & 3;
    const int n0   = blockIdx.y * 128;

    float acc[4][4][4] = {};

    auto loadTiles = [&](int buf, int k0) {
        // A: 128 rows x 16 k -> permuted half2 pairs
        #pragma unroll
        for (int p = 0; p < 2; p++) {
            int idx = p * 256 + tid;
            int row = idx >> 2;
            int q   = idx & 3;             // k quarter: k = q*4 .. q*4+3
            int gr  = n0 + row;
            float4 v = make_float4(0.f, 0.f, 0.f, 0.f);
            if (gr < N) v = *(const float4*)(A + (size_t)gr * K + k0 + q * 4);
            __half2 h0 = __floats2half2_rn(v.x, v.y);   // kpair 2q
            __half2 h1 = __floats2half2_rn(v.z, v.w);   // kpair 2q+1
            const int kp0 = 2 * q, kp1 = 2 * q + 1;
            As2[buf][row][(kp0 & 3) * 2 + (kp0 >> 2)] = *(unsigned*)&h0;
            As2[buf][row][(kp1 & 3) * 2 + (kp1 >> 2)] = *(unsigned*)&h1;
        }
        // B: 8 kpairs x 128 n
        #pragma unroll
        for (int p = 0; p < 4; p++) {
            int idx = p * 256 + tid;
            int kp = idx >> 7;
            int n  = idx & 127;
            float a = B[(size_t)(k0 + 2 * kp)     * Mb + m0 + n];
            float b = B[(size_t)(k0 + 2 * kp + 1) * Mb + m0 + n];
            __half2 h = __floats2half2_rn(a, b);
            Bs2[buf][kp][n] = *(unsigned*)&h;
        }
    };

    loadTiles(0, 0);
    __syncthreads();

    const int nk = K / 16;
    for (int kt = 0; kt < nk; kt++) {
        const int buf = kt & 1;
        if (kt + 1 < nk) loadTiles(buf ^ 1, (kt + 1) * 16);

        uint2 alo[4], ahi[4];
        #pragma unroll
        for (int mi = 0; mi < 4; mi++) {
            int rb = wm * 64 + mi * 16 + grp;
            alo[mi] = *(const uint2*)&As2[buf][rb][2 * tig];
            ahi[mi] = *(const uint2*)&As2[buf][rb + 8][2 * tig];
        }
        unsigned bfr[4][2];
        #pragma unroll
        for (int ni = 0; ni < 4; ni++) {
            int nb = wn * 32 + ni * 8 + grp;
            bfr[ni][0] = Bs2[buf][tig    ][nb];
            bfr[ni][1] = Bs2[buf][tig + 4][nb];
        }

        #pragma unroll
        for (int mi = 0; mi < 4; mi++)
            #pragma unroll
            for (int ni = 0; ni < 4; ni++)
                mma_f16(acc[mi][ni], alo[mi].x, ahi[mi].x, alo[mi].y, ahi[mi].y,
                        bfr[ni][0], bfr[ni][1]);
        __syncthreads();
    }

    #pragma unroll
    for (int mi = 0; mi < 4; mi++) {
        int r0 = n0 + wm * 64 + mi * 16 + grp;
        int r1 = r0 + 8;
        #pragma unroll
        for (int ni = 0; ni < 4; ni++) {
            int col = ccol0 + m0 + wn * 32 + ni * 8 + tig * 2;
            if (r0 < N)
                *(float2*)(Cp + (size_t)r0 * Mc + col) = make_float2(acc[mi][ni][0], acc[mi][ni][1]);
            if (r1 < N)
                *(float2*)(Cp + (size_t)r1 * Mc + col) = make_float2(acc[mi][ni][2], acc[mi][ni][3]);
        }
    }
}

// ---------------- fused GATv2 edge kernel (lane-group edge parallelism) ----------
// block = dst node, warp = head. No running max (|e| << 88 at this scale:
// ratio identical to max-subtracted reference). Lanes split into GROUPS groups;
// group g owns edges j+g; shuffles/exps shared across groups in the same
// instructions. OOB groups: clamped index + exact w=0. Per-group S/V merged once.
template <int C, bool CONCAT, int STRIDE, int GROUPS>
__global__ void __launch_bounds__(HEADS * 32)
gat_fused_kernel(const float* __restrict__ xl, const float* __restrict__ xr,
                 const float* __restrict__ att, const float* __restrict__ bias,
                 float* __restrict__ out, float* __restrict__ hout,
                 const float* __restrict__ Wo, const float* __restrict__ bo,
                 float* __restrict__ outp) {
    constexpr int GSIZE = 32 / GROUPS;
    constexpr int VEC   = C / GSIZE;
    constexpr int NV4   = VEC / 4;
    const int d    = blockIdx.x;
    const int h    = threadIdx.x >> 5;
    const int lane = threadIdx.x & 31;
    const int g    = lane / GSIZE;
    const int sl   = lane % GSIZE;
    const int row_off = h * C + sl * VEC;

    float xrv[VEC], attv[VEC];
    #pragma unroll
    for (int i = 0; i < NV4; i++) {
        float4 t = *(const float4*)(xr + (size_t)d * STRIDE + row_off + 4 * i);
        xrv[4*i+0] = t.x; xrv[4*i+1] = t.y; xrv[4*i+2] = t.z; xrv[4*i+3] = t.w;
        t = *(const float4*)(att + row_off + 4 * i);
        attv[4*i+0] = t.x; attv[4*i+1] = t.y; attv[4*i+2] = t.z; attv[4*i+3] = t.w;
    }

    const int row = g_rowptr[d];
    const int end = g_rowptr[d + 1];

    float S = 0.f;
    float V[VEC];
    #pragma unroll
    for (int i = 0; i < VEC; i++) V[i] = 0.f;

    auto ld = [&](int j, float* dst) {
        const int jj = min(j + g, end - 1);
        const float* p = xl + (size_t)g_csr_src[jj] * STRIDE + row_off;
        #pragma unroll
        for (int i = 0; i < NV4; i++) {
            float4 t = ((const float4*)p)[i];
            dst[4*i+0] = t.x; dst[4*i+1] = t.y; dst[4*i+2] = t.z; dst[4*i+3] = t.w;
        }
    };

    auto proc = [&](const float* x, int j) {
        float p = 0.f;
        #pragma unroll
        for (int i = 0; i < VEC; i++) {
            float m = x[i] + xrv[i];
            p += (m > 0.f ? m : NEG_SLOPE * m) * attv[i];
        }
        #pragma unroll
        for (int off = GSIZE / 2; off >= 1; off >>= 1)
            p += __shfl_xor_sync(0xffffffffu, p, off);
        const float w = (j + g < end) ? __expf(p) : 0.f;
        S += w;
        #pragma unroll
        for (int i = 0; i < VEC; i++) V[i] += w * x[i];
    };

    float xa[VEC], xb[VEC];
    ld(row, xa);
    if (row + GROUPS < end) ld(row + GROUPS, xb);

    for (int j = row; j < end; j += 2 * GROUPS) {
        float x0[VEC];
        #pragma unroll
        for (int i = 0; i < VEC; i++) x0[i] = xa[i];
        if (j + 2 * GROUPS < end) ld(j + 2 * GROUPS, xa);
        proc(x0, j);
        if (j + GROUPS < end) {
            float x1[VEC];
            #pragma unroll
            for (int i = 0; i < VEC; i++) x1[i] = xb[i];
            if (j + 3 * GROUPS < end) ld(j + 3 * GROUPS, xb);
            proc(x1, j + GROUPS);
        }
    }

    __shared__ float sV[GROUPS][HEADS * C];
    __shared__ float sS[GROUPS][HEADS];
    #pragma unroll
    for (int i = 0; i < VEC; i++) sV[g][row_off + i] = V[i];
    if (sl == 0) sS[g][h] = S;
    __syncthreads();

    const int t = threadIdx.x;   // 128 threads
    if constexpr (CONCAT) {
        const int th = t / C;
        float s = 0.f, v = 0.f;
        #pragma unroll
        for (int gg = 0; gg < GROUPS; gg++) { s += sS[gg][th]; v += sV[gg][t]; }
        float o = v / s + bias[t];
        out[(size_t)d * (HEADS * C) + t] = o > 0.f ? o : 0.f;
    } else {
        float acc = 0.f;
        #pragma unroll
        for (int hh = 0; hh < HEADS; hh++) {
            float s = 0.f, v = 0.f;
            #pragma unroll
            for (int gg = 0; gg < GROUPS; gg++) { s += sS[gg][hh]; v += sV[gg][hh * C + t]; }
            acc += v / s;
        }
        float o = acc * 0.25f + bias[t];
        if (hout) hout[(size_t)d * C + t] = o;

        if (outp) {
            __shared__ float red0[128], red1[128];
            red0[t] = o * Wo[2 * t];
            red1[t] = o * Wo[2 * t + 1];
            __syncthreads();
            #pragma unroll
            for (int s2 = 64; s2 > 0; s2 >>= 1) {
                if (t < s2) { red0[t] += red0[t + s2]; red1[t] += red1[t + s2]; }
                __syncthreads();
            }
            if (t == 0) {
                outp[2 * d + 0] = red0[0] + bo[0];
                outp[2 * d + 1] = red1[0] + bo[1];
            }
        }
    }
}

// ---------------- launch ---------------------------------------------------------
static inline int cdiv(int a, int b) { return (a + b - 1) / b; }

extern "C" void kernel_launch(void* const* d_in, const int* in_sizes, int n_in,
                              void* d_out, int out_size) {
    const float* x    = (const float*)d_in[0];
    const void*  ei   = d_in[1];
    const float* Wl1  = (const float*)d_in[2];
    const float* Wr1  = (const float*)d_in[3];
    const float* att1 = (const float*)d_in[4];
    const float* b1   = (const float*)d_in[5];
    const float* Wl2  = (const float*)d_in[6];
    const float* Wr2  = (const float*)d_in[7];
    const float* att2 = (const float*)d_in[8];
    const float* b2   = (const float*)d_in[9];
    const float* Wo   = (const float*)d_in[10];
    const float* bo   = (const float*)d_in[11];

    float* outf = (float*)d_out;
    float* outp = nullptr;
    float* hp   = nullptr;
    if (out_size >= N_NODES * (OUT_DIM + C2)) { outp = outf; hp = outf + (size_t)N_NODES * OUT_DIM; }
    else if (out_size == N_NODES * C2)        { hp = outf; }
    else                                       { outp = outf; }

    float *xlr1, *h1, *xl2, *xr2;
    int* degp;
    cudaGetSymbolAddress((void**)&xlr1, g_xlr1);
    cudaGetSymbolAddress((void**)&h1,   g_h1);
    cudaGetSymbolAddress((void**)&xl2,  g_xl2);
    cudaGetSymbolAddress((void**)&xr2,  g_xr2);
    cudaGetSymbolAddress((void**)&degp, g_deg);

    const int T = 256;
    cudaStream_t main0 = 0;   // harness capture stream

    // ---- fork: CSR chain on g_s1, layer-1 GEMM on main ----
    cudaMemsetAsync(degp, 0, N_NODES * sizeof(int), main0);
    cudaEventRecord(g_e0, main0);
    cudaStreamWaitEvent(g_s1, g_e0, 0);

    build_edges_kernel<<<cdiv(E_TOT, T), T, 0, g_s1>>>(ei);                  // #1
    {
        dim3 g(2, cdiv(N_NODES, 128));   // block 0: Wl1 -> cols [0,128); 1: Wr1 -> [128,256)
        sgemm_f16<<<g, 256, 0, main0>>>(x, Wl1, Wr1, xlr1, xlr1,
                                        N_NODES, F_IN, D1, 2 * D1, 1, D1);   // #2
    }
    scan1_kernel<<<SCAN_NB, SCAN_B, 0, g_s1>>>();                            // #3
    scan3_kernel<<<cdiv(N_NODES, T), T, 0, g_s1>>>();                        // #4
    scatter_kernel<<<cdiv(E_TOT, T), T, 0, g_s1>>>();                        // #5
    cudaEventRecord(g_e1, g_s1);
    cudaStreamWaitEvent(main0, g_e1, 0);

    // ---- layer-1 edge phase (4 groups x 8 lanes) ----
    gat_fused_kernel<C1, true, 2 * D1, 4><<<N_NODES, HEADS * 32, 0, main0>>>( // #6
        xlr1, xlr1 + D1, att1, b1, h1, nullptr, nullptr, nullptr, nullptr);

    // ---- layer-2 GEMMs: one launch, both halves ----
    {
        dim3 g(8, cdiv(N_NODES, 128));   // blocks 0-3: Wl2->xl2, 4-7: Wr2->xr2
        sgemm_f16<<<g, 256, 0, main0>>>(h1, Wl2, Wr2, xl2, xr2,
                                        N_NODES, D1, D2, D2, 4, 0);           // #7
    }

    // ---- layer-2 edge phase (2 groups x 16 lanes, + fused decoder) ----
    gat_fused_kernel<C2, false, D2, 2><<<N_NODES, HEADS * 32, 0, main0>>>(    // #8
        xl2, xr2, att2, b2, nullptr, hp, Wo, bo, outp);
}

// round 16
// speedup vs baseline: 1.1596x; 1.0125x over previous
#include <cuda_runtime.h>
#include <cuda_fp16.h>
#include <cstdint>

#define N_NODES 50000
#define N_EDGES 800000
#define E_TOT   (N_EDGES + N_NODES)   // 850000 (self-loops appended)
#define F_IN    128
#define HEADS   4
#define C1      32
#define C2      128
#define D1      (HEADS * C1)          // 128
#define D2      (HEADS * C2)          // 512
#define OUT_DIM 2
#define NEG_SLOPE 0.2f

#define SCAN_B  1024
#define SCAN_NB ((N_NODES + SCAN_B - 1) / SCAN_B)   // 49

#define W1H_SZ  (64 * 128)            // half2 entries per W1 matrix
#define W2H_SZ  (64 * 512)            // half2 entries per W2 matrix
#define XH_SZ   (N_NODES * F_IN / 2)  // half2 entries of x

// ---------------- device scratch (static; no cudaMalloc allowed) ---------------
__device__ float    g_xlr1[N_NODES * 2 * D1];  // [xl1|xr1] fp32 (stride 256)
__device__ __half   g_h1h[N_NODES * D1];       // h1 in fp16 (GEMM2 A input)
__device__ float    g_xl2[N_NODES * D2];
__device__ float    g_xr2[N_NODES * D2];
__device__ unsigned g_xh[XH_SZ];               // x as half2
__device__ unsigned g_w1h[2 * W1H_SZ];         // W1 l|r, kpair-interleaved half2
__device__ unsigned g_w2h[2 * W2H_SZ];         // W2 l|r, kpair-interleaved half2
__device__ int      g_src[E_TOT];
__device__ int      g_dst[E_TOT];
__device__ int      g_deg[N_NODES];
__device__ int      g_rowptr[N_NODES + 1];
__device__ int      g_cursor[N_NODES];
__device__ int      g_csr_src[E_TOT];
__device__ int      g_blocksum[SCAN_NB];

// ---------------- host-side stream/event objects (created pre-main) -------------
static cudaStream_t g_s1;
static cudaEvent_t  g_e0, g_e1;
static const bool g_init = [] {
    cudaStreamCreateWithFlags(&g_s1, cudaStreamNonBlocking);
    cudaEventCreateWithFlags(&g_e0, cudaEventDisableTiming);
    cudaEventCreateWithFlags(&g_e1, cudaEventDisableTiming);
    return true;
}();

// ---------------- weight / input fp16 pre-conversion -----------------------------
// Pre-converting is bit-identical to the per-tile cvt the GEMM used to do.
// Layout: Bh2[kp * M + n] = half2(W[2kp][n], W[2kp+1][n]).
__global__ void convw_kernel(const float* __restrict__ Wl1, const float* __restrict__ Wr1,
                             const float* __restrict__ Wl2, const float* __restrict__ Wr2) {
    int i = blockIdx.x * blockDim.x + threadIdx.x;
    if (i >= 2 * W1H_SZ + 2 * W2H_SZ) return;
    const float* src;
    unsigned* dst;
    int M, j;
    if (i < 2 * W1H_SZ) {
        j = (i < W1H_SZ) ? i : i - W1H_SZ;
        src = (i < W1H_SZ) ? Wl1 : Wr1;
        dst = (i < W1H_SZ) ? g_w1h : g_w1h + W1H_SZ;
        M = D1;
    } else {
        int q = i - 2 * W1H_SZ;
        j = (q < W2H_SZ) ? q : q - W2H_SZ;
        src = (q < W2H_SZ) ? Wl2 : Wr2;
        dst = (q < W2H_SZ) ? g_w2h : g_w2h + W2H_SZ;
        M = D2;
    }
    const int kp = j / M, n = j % M;
    __half2 h = __floats2half2_rn(src[(size_t)(2 * kp) * M + n],
                                  src[(size_t)(2 * kp + 1) * M + n]);
    dst[j] = *(unsigned*)&h;
}

__global__ void convx_kernel(const float* __restrict__ x) {
    int i = blockIdx.x * blockDim.x + threadIdx.x;
    if (i >= XH_SZ) return;
    float2 v = ((const float2*)x)[i];
    __half2 h = __floats2half2_rn(v.x, v.y);
    g_xh[i] = *(unsigned*)&h;
}

// ---------------- edge build (dtype detected per block) --------------------------
__global__ void build_edges_kernel(const void* __restrict__ ei) {
    int nz = 0;
    for (int i = threadIdx.x; i < 512; i += blockDim.x)
        nz |= ((const int*)ei)[2 * i + 1];
    nz = __syncthreads_or(nz);
    const bool is64 = (nz == 0);

    int i = blockIdx.x * blockDim.x + threadIdx.x;
    if (i >= E_TOT) return;
    int s, d;
    if (i < N_EDGES) {
        if (is64) {
            const long long* p = (const long long*)ei;
            s = (int)p[i];
            d = (int)p[N_EDGES + i];
        } else {
            const int* p = (const int*)ei;
            s = p[i];
            d = p[N_EDGES + i];
        }
    } else {
        s = d = i - N_EDGES;
    }
    g_src[i] = s;
    g_dst[i] = d;
    atomicAdd(&g_deg[d], 1);
}

// ---------------- parallel exclusive scan (2 kernels) ----------------------------
__global__ void scan1_kernel() {
    __shared__ int sh[SCAN_B];
    const int tid = threadIdx.x;
    const int idx = blockIdx.x * SCAN_B + tid;
    int v = (idx < N_NODES) ? g_deg[idx] : 0;
    sh[tid] = v;
    __syncthreads();
    #pragma unroll
    for (int off = 1; off < SCAN_B; off <<= 1) {
        int t = (tid >= off) ? sh[tid - off] : 0;
        __syncthreads();
        sh[tid] += t;
        __syncthreads();
    }
    if (idx < N_NODES) g_rowptr[idx] = sh[tid] - v;
    if (tid == SCAN_B - 1) g_blocksum[blockIdx.x] = sh[tid];
}

__global__ void scan3_kernel() {
    __shared__ int vals[SCAN_NB];
    __shared__ int off;
    const int tid = threadIdx.x;
    if (tid < SCAN_NB) vals[tid] = g_blocksum[tid];
    __syncthreads();
    if (tid == 0) {
        const int b = (blockIdx.x * blockDim.x) / SCAN_B;
        int acc = 0;
        for (int i = 0; i < b; i++) acc += vals[i];
        off = acc;
    }
    __syncthreads();
    const int idx = blockIdx.x * blockDim.x + tid;
    if (idx < N_NODES) {
        int r = g_rowptr[idx] + off;
        g_rowptr[idx] = r;
        g_cursor[idx] = r;
    }
    if (idx == 0) g_rowptr[N_NODES] = E_TOT;
}

__global__ void scatter_kernel() {
    int i = blockIdx.x * blockDim.x + threadIdx.x;
    if (i >= E_TOT) return;
    int d = g_dst[i];
    int pos = atomicAdd(&g_cursor[d], 1);
    g_csr_src[pos] = g_src[i];
}

// ---------------- FP16 tensor-core GEMM (m16n8k16, fp32 acc, half inputs) --------
// A: half row-major [N][K]. B: pre-interleaved half2, Bh2[kp*Mb + n].
// grid.x = 2*halfX: first half computes Ca = A@Ba, second Cb = A@Bb at col coff.
__device__ __forceinline__ void mma_f16(float* d, unsigned a0, unsigned a1,
                                        unsigned a2, unsigned a3,
                                        unsigned b0, unsigned b1) {
    asm volatile(
        "mma.sync.aligned.m16n8k16.row.col.f32.f16.f16.f32 "
        "{%0,%1,%2,%3}, {%4,%5,%6,%7}, {%8,%9}, {%0,%1,%2,%3};"
        : "+f"(d[0]), "+f"(d[1]), "+f"(d[2]), "+f"(d[3])
        : "r"(a0), "r"(a1), "r"(a2), "r"(a3), "r"(b0), "r"(b1));
}

__global__ void __launch_bounds__(256)
sgemm_h16(const __half* __restrict__ A,
          const unsigned* __restrict__ Bh2a, const unsigned* __restrict__ Bh2b,
          float* __restrict__ Ca, float* __restrict__ Cb,
          int N, int K, int Mb, int Mc, int halfX, int coff) {
    __shared__ unsigned As2[2][128][8];    // [buf][m][perm kpair] half2
    __shared__ unsigned Bs2[2][8][136];    // [buf][kpair][n] half2

    const bool second = (int)blockIdx.x >= halfX;
    const unsigned* Bh2 = second ? Bh2b : Bh2a;
    float* Cp           = second ? Cb : Ca;
    const int ccol0 = second ? coff : 0;
    const int m0 = ((int)blockIdx.x % halfX) * 128;

    const int tid  = threadIdx.x;
    const int wid  = tid >> 5;
    const int lane = tid & 31;
    const int grp  = lane >> 2;
    const int tig  = lane & 3;
    const int wm   = wid >> 2;
    const int wn   = wid & 3;
    const int n0   = blockIdx.y * 128;

    float acc[4][4][4] = {};

    auto loadTiles = [&](int buf, int k0) {
        // A: 128 rows x 16 halves -> permuted half2 slots (slot(kp)=(kp&3)*2+(kp>>2))
        {
            const int row = tid >> 1;
            const int h8  = (tid & 1) * 8;       // halves h8..h8+7 = kpairs kb..kb+3
            const int kb  = (tid & 1) * 4;
            const int gr  = n0 + row;
            uint4 u = make_uint4(0u, 0u, 0u, 0u);
            if (gr < N) u = *(const uint4*)(A + (size_t)gr * K + k0 + h8);
            As2[buf][row][((kb + 0) & 3) * 2 + ((kb + 0) >> 2)] = u.x;
            As2[buf][row][((kb + 1) & 3) * 2 + ((kb + 1) >> 2)] = u.y;
            As2[buf][row][((kb + 2) & 3) * 2 + ((kb + 2) >> 2)] = u.z;
            As2[buf][row][((kb + 3) & 3) * 2 + ((kb + 3) >> 2)] = u.w;
        }
        // B: 8 kpairs x 128 n, straight uint4 copy of pre-interleaved half2
        {
            const int kp = tid >> 5;
            const int n4 = (tid & 31) * 4;
            uint4 v = *(const uint4*)(Bh2 + (size_t)(k0 / 2 + kp) * Mb + m0 + n4);
            *(uint4*)&Bs2[buf][kp][n4] = v;
        }
    };

    loadTiles(0, 0);
    __syncthreads();

    const int nk = K / 16;
    for (int kt = 0; kt < nk; kt++) {
        const int buf = kt & 1;
        if (kt + 1 < nk) loadTiles(buf ^ 1, (kt + 1) * 16);

        uint2 alo[4], ahi[4];
        #pragma unroll
        for (int mi = 0; mi < 4; mi++) {
            int rb = wm * 64 + mi * 16 + grp;
            alo[mi] = *(const uint2*)&As2[buf][rb][2 * tig];
            ahi[mi] = *(const uint2*)&As2[buf][rb + 8][2 * tig];
        }
        unsigned bfr[4][2];
        #pragma unroll
        for (int ni = 0; ni < 4; ni++) {
            int nb = wn * 32 + ni * 8 + grp;
            bfr[ni][0] = Bs2[buf][tig    ][nb];
            bfr[ni][1] = Bs2[buf][tig + 4][nb];
        }

        #pragma unroll
        for (int mi = 0; mi < 4; mi++)
            #pragma unroll
            for (int ni = 0; ni < 4; ni++)
                mma_f16(acc[mi][ni], alo[mi].x, ahi[mi].x, alo[mi].y, ahi[mi].y,
                        bfr[ni][0], bfr[ni][1]);
        __syncthreads();
    }

    #pragma unroll
    for (int mi = 0; mi < 4; mi++) {
        int r0 = n0 + wm * 64 + mi * 16 + grp;
        int r1 = r0 + 8;
        #pragma unroll
        for (int ni = 0; ni < 4; ni++) {
            int col = ccol0 + m0 + wn * 32 + ni * 8 + tig * 2;
            if (r0 < N)
                *(float2*)(Cp + (size_t)r0 * Mc + col) = make_float2(acc[mi][ni][0], acc[mi][ni][1]);
            if (r1 < N)
                *(float2*)(Cp + (size_t)r1 * Mc + col) = make_float2(acc[mi][ni][2], acc[mi][ni][3]);
        }
    }
}

// ---------------- fused GATv2 edge kernel (lane-group edge parallelism) ----------
// block = dst node, warp = head. No running max (|e| << 88 at this scale:
// ratio identical to max-subtracted reference). Lanes split into GROUPS groups;
// group g owns edges j+g; shuffles/exps shared across groups in the same
// instructions. OOB groups: clamped index + exact w=0. Per-group S/V merged once.
// CONCAT epilogue writes fp16 (bit-identical to GEMM2's own A-load rounding).
template <int C, bool CONCAT, int STRIDE, int GROUPS>
__global__ void __launch_bounds__(HEADS * 32)
gat_fused_kernel(const float* __restrict__ xl, const float* __restrict__ xr,
                 const float* __restrict__ att, const float* __restrict__ bias,
                 __half* __restrict__ outh, float* __restrict__ hout,
                 const float* __restrict__ Wo, const float* __restrict__ bo,
                 float* __restrict__ outp) {
    constexpr int GSIZE = 32 / GROUPS;
    constexpr int VEC   = C / GSIZE;
    constexpr int NV4   = VEC / 4;
    const int d    = blockIdx.x;
    const int h    = threadIdx.x >> 5;
    const int lane = threadIdx.x & 31;
    const int g    = lane / GSIZE;
    const int sl   = lane % GSIZE;
    const int row_off = h * C + sl * VEC;

    float xrv[VEC], attv[VEC];
    #pragma unroll
    for (int i = 0; i < NV4; i++) {
        float4 t = *(const float4*)(xr + (size_t)d * STRIDE + row_off + 4 * i);
        xrv[4*i+0] = t.x; xrv[4*i+1] = t.y; xrv[4*i+2] = t.z; xrv[4*i+3] = t.w;
        t = *(const float4*)(att + row_off + 4 * i);
        attv[4*i+0] = t.x; attv[4*i+1] = t.y; attv[4*i+2] = t.z; attv[4*i+3] = t.w;
    }

    const int row = g_rowptr[d];
    const int end = g_rowptr[d + 1];

    float S = 0.f;
    float V[VEC];
    #pragma unroll
    for (int i = 0; i < VEC; i++) V[i] = 0.f;

    auto ld = [&](int j, float* dst) {
        const int jj = min(j + g, end - 1);
        const float* p = xl + (size_t)g_csr_src[jj] * STRIDE + row_off;
        #pragma unroll
        for (int i = 0; i < NV4; i++) {
            float4 t = ((const float4*)p)[i];
            dst[4*i+0] = t.x; dst[4*i+1] = t.y; dst[4*i+2] = t.z; dst[4*i+3] = t.w;
        }
    };

    auto proc = [&](const float* x, int j) {
        float p = 0.f;
        #pragma unroll
        for (int i = 0; i < VEC; i++) {
            float m = x[i] + xrv[i];
            p += (m > 0.f ? m : NEG_SLOPE * m) * attv[i];
        }
        #pragma unroll
        for (int off = GSIZE / 2; off >= 1; off >>= 1)
            p += __shfl_xor_sync(0xffffffffu, p, off);
        const float w = (j + g < end) ? __expf(p) : 0.f;
        S += w;
        #pragma unroll
        for (int i = 0; i < VEC; i++) V[i] += w * x[i];
    };

    float xa[VEC], xb[VEC];
    ld(row, xa);
    if (row + GROUPS < end) ld(row + GROUPS, xb);

    for (int j = row; j < end; j += 2 * GROUPS) {
        float x0[VEC];
        #pragma unroll
        for (int i = 0; i < VEC; i++) x0[i] = xa[i];
        if (j + 2 * GROUPS < end) ld(j + 2 * GROUPS, xa);
        proc(x0, j);
        if (j + GROUPS < end) {
            float x1[VEC];
            #pragma unroll
            for (int i = 0; i < VEC; i++) x1[i] = xb[i];
            if (j + 3 * GROUPS < end) ld(j + 3 * GROUPS, xb);
            proc(x1, j + GROUPS);
        }
    }

    __shared__ float sV[GROUPS][HEADS * C];
    __shared__ float sS[GROUPS][HEADS];
    #pragma unroll
    for (int i = 0; i < VEC; i++) sV[g][row_off + i] = V[i];
    if (sl == 0) sS[g][h] = S;
    __syncthreads();

    const int t = threadIdx.x;   // 128 threads
    if constexpr (CONCAT) {
        const int th = t / C;
        float s = 0.f, v = 0.f;
        #pragma unroll
        for (int gg = 0; gg < GROUPS; gg++) { s += sS[gg][th]; v += sV[gg][t]; }
        float o = v / s + bias[t];
        o = o > 0.f ? o : 0.f;
        outh[(size_t)d * (HEADS * C) + t] = __float2half_rn(o);
    } else {
        float acc = 0.f;
        #pragma unroll
        for (int hh = 0; hh < HEADS; hh++) {
            float s = 0.f, v = 0.f;
            #pragma unroll
            for (int gg = 0; gg < GROUPS; gg++) { s += sS[gg][hh]; v += sV[gg][hh * C + t]; }
            acc += v / s;
        }
        float o = acc * 0.25f + bias[t];
        if (hout) hout[(size_t)d * C + t] = o;

        if (outp) {
            __shared__ float red0[128], red1[128];
            red0[t] = o * Wo[2 * t];
            red1[t] = o * Wo[2 * t + 1];
            __syncthreads();
            #pragma unroll
            for (int s2 = 64; s2 > 0; s2 >>= 1) {
                if (t < s2) { red0[t] += red0[t + s2]; red1[t] += red1[t + s2]; }
                __syncthreads();
            }
            if (t == 0) {
                outp[2 * d + 0] = red0[0] + bo[0];
                outp[2 * d + 1] = red1[0] + bo[1];
            }
        }
    }
}

// ---------------- launch ---------------------------------------------------------
static inline int cdiv(int a, int b) { return (a + b - 1) / b; }

extern "C" void kernel_launch(void* const* d_in, const int* in_sizes, int n_in,
                              void* d_out, int out_size) {
    const float* x    = (const float*)d_in[0];
    const void*  ei   = d_in[1];
    const float* Wl1  = (const float*)d_in[2];
    const float* Wr1  = (const float*)d_in[3];
    const float* att1 = (const float*)d_in[4];
    const float* b1   = (const float*)d_in[5];
    const float* Wl2  = (const float*)d_in[6];
    const float* Wr2  = (const float*)d_in[7];
    const float* att2 = (const float*)d_in[8];
    const float* b2   = (const float*)d_in[9];
    const float* Wo   = (const float*)d_in[10];
    const float* bo   = (const float*)d_in[11];

    float* outf = (float*)d_out;
    float* outp = nullptr;
    float* hp   = nullptr;
    if (out_size >= N_NODES * (OUT_DIM + C2)) { outp = outf; hp = outf + (size_t)N_NODES * OUT_DIM; }
    else if (out_size == N_NODES * C2)        { hp = outf; }
    else                                       { outp = outf; }

    float *xlr1, *xl2, *xr2;
    __half *h1h, *xh;
    unsigned *w1h, *w2h;
    int* degp;
    cudaGetSymbolAddress((void**)&xlr1, g_xlr1);
    cudaGetSymbolAddress((void**)&h1h,  g_h1h);
    cudaGetSymbolAddress((void**)&xl2,  g_xl2);
    cudaGetSymbolAddress((void**)&xr2,  g_xr2);
    cudaGetSymbolAddress((void**)&xh,   g_xh);
    cudaGetSymbolAddress((void**)&w1h,  g_w1h);
    cudaGetSymbolAddress((void**)&w2h,  g_w2h);
    cudaGetSymbolAddress((void**)&degp, g_deg);

    const int T = 256;
    cudaStream_t main0 = 0;   // harness capture stream

    // ---- fork: CSR chain on g_s1; conversions + layer-1 GEMM on main ----
    cudaMemsetAsync(degp, 0, N_NODES * sizeof(int), main0);
    cudaEventRecord(g_e0, main0);
    cudaStreamWaitEvent(g_s1, g_e0, 0);

    convw_kernel<<<cdiv(2 * W1H_SZ + 2 * W2H_SZ, T), T, 0, main0>>>(Wl1, Wr1, Wl2, Wr2); // #1
    convx_kernel<<<cdiv(XH_SZ, T), T, 0, main0>>>(x);                                    // #2
    build_edges_kernel<<<cdiv(E_TOT, T), T, 0, g_s1>>>(ei);                              // #3
    {
        dim3 g(2, cdiv(N_NODES, 128));   // block 0: W1l -> cols [0,128); 1: W1r -> [128,256)
        sgemm_h16<<<g, 256, 0, main0>>>(xh, w1h, w1h + W1H_SZ, xlr1, xlr1,
                                        N_NODES, F_IN, D1, 2 * D1, 1, D1);               // #4 (ncu)
    }
    scan1_kernel<<<SCAN_NB, SCAN_B, 0, g_s1>>>();                                        // #5
    scan3_kernel<<<cdiv(N_NODES, T), T, 0, g_s1>>>();                                    // #6
    scatter_kernel<<<cdiv(E_TOT, T), T, 0, g_s1>>>();                                    // #7
    cudaEventRecord(g_e1, g_s1);
    cudaStreamWaitEvent(main0, g_e1, 0);

    // ---- layer-1 edge phase (4 groups x 8 lanes, fp16 h1 output) ----
    gat_fused_kernel<C1, true, 2 * D1, 4><<<N_NODES, HEADS * 32, 0, main0>>>(            // #8
        xlr1, xlr1 + D1, att1, b1, h1h, nullptr, nullptr, nullptr, nullptr);

    // ---- layer-2 GEMMs: one launch, both halves, half inputs ----
    {
        dim3 g(8, cdiv(N_NODES, 128));   // blocks 0-3: W2l->xl2, 4-7: W2r->xr2
        sgemm_h16<<<g, 256, 0, main0>>>(h1h, w2h, w2h + W2H_SZ, xl2, xr2,
                                        N_NODES, D1, D2, D2, 4, 0);                      // #9
    }

    // ---- layer-2 edge phase (2 groups x 16 lanes, + fused decoder) ----
    gat_fused_kernel<C2, false, D2, 2><<<N_NODES, HEADS * 32, 0, main0>>>(               // #10
        xl2, xr2, att2, b2, nullptr, hp, Wo, bo, outp);
}